// round 11
// baseline (speedup 1.0000x reference)
#include <cuda_runtime.h>
#include <math.h>

#define Bsz 256
#define Xd  256
#define Hd  512
#define Rd  128
#define Md  128
#define Td  256
#define XHD 768      // X+H
#define CATD 896     // X+H+R
#define NPRE 2176    // R+4H columns of W_full
#define NG1 640      // R+H
#define ODIM 640
#define GRID 148

typedef unsigned long long ull;

// persistent state / scratch (device globals; no allocation)
__device__ float g_c[Bsz*Hd];
__device__ float g_hmem[Bsz*Md*Rd];
__device__ float g_hent[Bsz*Rd];
__device__ int   g_sel[Bsz];
__device__ float g_fcwxT[Xd*Md];      // fc_w x-part transposed (k-major)
__device__ float g_wcomb[Hd*256];     // [k][0:128]=fc_w c-part^T, [k][128:256]=trans_w^T
__device__ float g_xh[Td*Bsz*Md];     // precomputed x-part of head (+fc_b)
__device__ float g_cc2s[Bsz*NG1];     // scaled [c|hent] part of concat
__device__ float g_g1p[14][Bsz*NG1];  // gates1 K-chunk partials
__device__ float g_prep[4][Bsz*NPRE]; // big GEMM K-chunk partials
__device__ float g_tp[32][Bsz*256];   // tail GEMM K-chunk partials

// grid barrier state: per-block flag slots (128B apart) + generation word
__device__ unsigned g_flags[GRID*32];
__device__ volatile unsigned g_bar_gen;

__device__ __forceinline__ float sigf(float v){ return 1.0f/(1.0f+expf(-v)); }
__device__ __forceinline__ ull pack2(float v){ ull r; asm("mov.b64 %0, {%1, %1};" : "=l"(r) : "f"(v)); return r; }
__device__ __forceinline__ void ffma2(ull &d, ull a, ull b){ asm("fma.rn.f32x2 %0, %1, %2, %0;" : "+l"(d) : "l"(a), "l"(b)); }
__device__ __forceinline__ float2 unpk(ull v){ float2 f; asm("mov.b64 {%0, %1}, %2;" : "=f"(f.x), "=f"(f.y) : "l"(v)); return f; }
__device__ __forceinline__ float4 ld4(const float* p){ return *(const float4*)p; }

// low-contention grid barrier: per-block flag STG + block0 aggregation + gen publish
__device__ __forceinline__ void gridbar(unsigned gen, int bid, int tid)
{
    __syncthreads();
    if (bid == 0){
        if (tid >= 1 && tid < GRID){
            volatile unsigned* f = &g_flags[tid*32];
            while (*f < gen) { __nanosleep(64); }
        }
        __syncthreads();
        if (tid == 0){
            __threadfence();      // order + L1 invalidate for block 0
            g_bar_gen = gen;
        }
    } else {
        if (tid == 0){
            __threadfence();      // make this block's stores visible first
            *((volatile unsigned*)&g_flags[bid*32]) = gen;
            while (g_bar_gen < gen) { __nanosleep(64); }
            __threadfence();      // L1 invalidate before block reads fresh data
        }
    }
    __syncthreads();
}

// ---------------- init ----------------
__global__ void k_init(const float* __restrict__ fc_w, const float* __restrict__ trans_w,
                       const float* __restrict__ c_bias, const float* __restrict__ hmem_bias)
{
    int idx = blockIdx.x*blockDim.x + threadIdx.x;
    if (idx == 0) g_bar_gen = 0u;
    if (idx < GRID*32) g_flags[idx] = 0u;
    if (idx < Bsz*Md*Rd) g_hmem[idx] = hmem_bias[idx & (Md*Rd-1)];
    if (idx < Bsz*Hd)    g_c[idx] = tanhf(c_bias[idx & (Hd-1)]);
    if (idx < Xd*Md){ int k = idx >> 7, m = idx & 127; g_fcwxT[idx] = fc_w[m*XHD + k]; }
    if (idx < Hd*256){
        int k = idx >> 8, c = idx & 255;
        g_wcomb[idx] = (c < 128) ? fc_w[c*XHD + Xd + k] : trans_w[(c-128)*Hd + k];
    }
}

// ---------------- Xh precompute ----------------
__global__ __launch_bounds__(256) void k_xhead(const float* __restrict__ x,
                                               const float* __restrict__ fc_b)
{
    __shared__ __align__(16) float As[16][68];
    __shared__ __align__(16) float Bs[16][128];
    const int tid = threadIdx.x;
    const int rb = blockIdx.x * 64;
    const int tm = tid >> 5;
    const int tn = tid & 31;

    ull acc[8][2] = {};

    const int ar = tid >> 2, akq = tid & 3;
    const float* Ap = x + (size_t)(rb + ar)*Xd + akq*4;
    const int bk = tid >> 4, bm = tid & 15;
    const float* Bp = g_fcwxT + (size_t)bk*Md + bm*8;

    float4 pa = ld4(Ap);
    float4 pb0 = ld4(Bp);
    float4 pb1 = ld4(Bp + 4);

    for (int kt = 0; kt < Xd/16; kt++) {
        As[akq*4+0][ar]=pa.x; As[akq*4+1][ar]=pa.y; As[akq*4+2][ar]=pa.z; As[akq*4+3][ar]=pa.w;
        *(float4*)&Bs[bk][bm*8]   = pb0;
        *(float4*)&Bs[bk][bm*8+4] = pb1;
        __syncthreads();
        if (kt+1 < Xd/16) {
            int k0 = (kt+1)*16;
            pa  = ld4(Ap + k0);
            pb0 = ld4(Bp + (size_t)k0*Md);
            pb1 = ld4(Bp + (size_t)k0*Md + 4);
        }
        #pragma unroll
        for (int kk = 0; kk < 16; kk++) {
            float4 a0 = *(const float4*)&As[kk][tm*8];
            float4 a1 = *(const float4*)&As[kk][tm*8+4];
            ulonglong2 bq = *(const ulonglong2*)&Bs[kk][tn*4];
            float a_[8] = {a0.x,a0.y,a0.z,a0.w,a1.x,a1.y,a1.z,a1.w};
            #pragma unroll
            for (int i=0;i<8;i++){
                ull ap = pack2(a_[i]);
                ffma2(acc[i][0], ap, bq.x);
                ffma2(acc[i][1], ap, bq.y);
            }
        }
        __syncthreads();
    }
    float4 fb = ld4(fc_b + tn*4);
    #pragma unroll
    for (int i=0;i<8;i++){
        int row = rb + tm*8 + i;
        float2 l0 = unpk(acc[i][0]), l1 = unpk(acc[i][1]);
        float4 o = { l0.x+fb.x, l0.y+fb.y, l1.x+fb.z, l1.y+fb.w };
        *(float4*)(g_xh + (size_t)row*Md + tn*4) = o;
    }
}

// ============ unified 128x128 GEMM unit (8x8 thread tile, FFMA2, double-buffered) ====

template<int MODE>
__device__ __forceinline__ float4 loadA(const float* __restrict__ x, int t, int row, int kg)
{
    if (MODE == 0){            // concat [x | c | hent]
        const float* p;
        if (kg < Xd)       p = x + ((size_t)t*Bsz + row)*Xd + kg;
        else if (kg < XHD) p = g_c + (size_t)row*Hd + (kg - Xd);
        else               p = g_hent + (size_t)row*Rd + (kg - XHD);
        return ld4(p);
    } else if (MODE == 1){     // [x | cc2s]
        const float* p = (kg < Xd) ? (x + ((size_t)t*Bsz + row)*Xd + kg)
                                   : (g_cc2s + (size_t)row*NG1 + (kg - Xd));
        return ld4(p);
    } else {                   // g_c
        return ld4(g_c + (size_t)row*Hd + kg);
    }
}

template<int MODE>
__device__ void gemm128(float* SM, const float* __restrict__ x, int t,
                        const float* __restrict__ Bm, int ldb,
                        int rb, int nb, int kbase, int nkt,
                        float* __restrict__ outP, int ldo)
{
    float (*As)[16][132] = (float(*)[16][132])SM;
    float (*Bs)[16][128] = (float(*)[16][128])(SM + 2*16*132);
    const int tid = threadIdx.x;
    const int tm = tid >> 4, tn = tid & 15;
    const int ia0 = tid*2, ia1 = tid*2+1;
    const int ar0 = ia0 >> 2, ak0 = (ia0 & 3)*4;
    const int ar1 = ia1 >> 2, ak1 = (ia1 & 3)*4;
    const int bk0 = ia0 >> 5, bc0 = (ia0 & 31)*4;
    const int bk1 = ia1 >> 5, bc1 = (ia1 & 31)*4;

    ull acc[8][4] = {};

    float4 pa0 = loadA<MODE>(x, t, rb+ar0, kbase + ak0);
    float4 pa1 = loadA<MODE>(x, t, rb+ar1, kbase + ak1);
    float4 pb0 = ld4(Bm + (size_t)(kbase + bk0)*ldb + nb + bc0);
    float4 pb1 = ld4(Bm + (size_t)(kbase + bk1)*ldb + nb + bc1);

    for (int kt = 0; kt < nkt; kt++){
        const int p = kt & 1;
        As[p][ak0+0][ar0]=pa0.x; As[p][ak0+1][ar0]=pa0.y; As[p][ak0+2][ar0]=pa0.z; As[p][ak0+3][ar0]=pa0.w;
        As[p][ak1+0][ar1]=pa1.x; As[p][ak1+1][ar1]=pa1.y; As[p][ak1+2][ar1]=pa1.z; As[p][ak1+3][ar1]=pa1.w;
        *(float4*)&Bs[p][bk0][bc0] = pb0;
        *(float4*)&Bs[p][bk1][bc1] = pb1;
        __syncthreads();
        if (kt+1 < nkt){
            int k0 = kbase + (kt+1)*16;
            pa0 = loadA<MODE>(x, t, rb+ar0, k0 + ak0);
            pa1 = loadA<MODE>(x, t, rb+ar1, k0 + ak1);
            pb0 = ld4(Bm + (size_t)(k0 + bk0)*ldb + nb + bc0);
            pb1 = ld4(Bm + (size_t)(k0 + bk1)*ldb + nb + bc1);
        }
        #pragma unroll
        for (int kk = 0; kk < 16; kk++){
            float4 a0 = *(const float4*)&As[p][kk][tm*8];
            float4 a1 = *(const float4*)&As[p][kk][tm*8+4];
            ulonglong2 b0 = *(const ulonglong2*)&Bs[p][kk][tn*8];
            ulonglong2 b1 = *(const ulonglong2*)&Bs[p][kk][tn*8+4];
            float av[8] = {a0.x,a0.y,a0.z,a0.w,a1.x,a1.y,a1.z,a1.w};
            ull bq[4] = {b0.x,b0.y,b1.x,b1.y};
            #pragma unroll
            for (int r = 0; r < 8; r++){
                ull ap = pack2(av[r]);
                ffma2(acc[r][0], ap, bq[0]);
                ffma2(acc[r][1], ap, bq[1]);
                ffma2(acc[r][2], ap, bq[2]);
                ffma2(acc[r][3], ap, bq[3]);
            }
        }
        __syncthreads();
    }
    #pragma unroll
    for (int r = 0; r < 8; r++){
        float2 c0 = unpk(acc[r][0]), c1 = unpk(acc[r][1]);
        float2 c2 = unpk(acc[r][2]), c3 = unpk(acc[r][3]);
        float* op = outP + (size_t)(rb + tm*8 + r)*ldo + nb + tn*8;
        float4 o0 = {c0.x, c0.y, c1.x, c1.y};
        float4 o1 = {c2.x, c2.y, c3.x, c3.y};
        *(float4*)op = o0;
        *(float4*)(op+4) = o1;
    }
}

// =========================== persistent-kernel phases ===============================

// G1: gates1 partials. 140 units = 10 tiles (128x128) x 14 K-chunks (K64).
__device__ void phG1(float* SM, const float* __restrict__ x,
                     const float* __restrict__ W1, int t, int bid)
{
    if (bid >= 140) return;
    const int tile = bid % 10, z = bid / 10;
    const int rb = (tile / 5) * 128, nb = (tile % 5) * 128;
    gemm128<0>(SM, x, t, W1, NG1, rb, nb, z*64, 4, g_g1p[z], NG1);
}

// G2: combine 14 partials, sigmoid-scale [c|hent] -> g_cc2s
__device__ void phG2(const float* __restrict__ bias1, int bid, int tid)
{
    for (int idx = bid*256 + tid; idx < Bsz*160; idx += GRID*256){
        int row = idx / 160;
        int c = (idx - row*160) * 4;
        size_t o = (size_t)row*NG1 + c;
        float4 s = ld4(g_g1p[0] + o);
        #pragma unroll
        for (int z = 1; z < 14; z++){
            float4 p = ld4(g_g1p[z] + o);
            s.x += p.x; s.y += p.y; s.z += p.z; s.w += p.w;
        }
        float4 b = ld4(bias1 + c);
        float4 cv = (c < Hd) ? ld4(g_c + (size_t)row*Hd + c)
                             : ld4(g_hent + (size_t)row*Rd + (c - Hd));
        float4 r;
        r.x = cv.x * sigf(s.x + b.x);
        r.y = cv.y * sigf(s.y + b.y);
        r.z = cv.z * sigf(s.z + b.z);
        r.w = cv.w * sigf(s.w + b.w);
        *(float4*)(g_cc2s + o) = r;
    }
}

// Big: 136 units = 34 tiles (128x128 plain cols) x 4 K-chunks (K224).
__device__ void phBig(float* SM, const float* __restrict__ x,
                      const float* __restrict__ Wf, int t, int bid)
{
    if (bid >= 136) return;
    const int tile = bid % 34, z = bid / 34;
    const int rb = (tile / 17) * 128, nb = (tile % 17) * 128;
    gemm128<1>(SM, x, t, Wf, NPRE, rb, nb, z*224, 14, g_prep[z], NPRE);
}

// C: combine 4 big partials + LSTM / r epilogue -> g_c, out
__device__ void phC(const float* __restrict__ bias, float* __restrict__ out,
                    int t, int bid, int tid)
{
    for (int idx = bid*256 + tid; idx < Bsz*Hd; idx += GRID*256){
        int row = idx >> 9, n = idx & 511;
        size_t base = (size_t)row*NPRE + n;
        float pi = 0.f, pj = 0.f, pf = 0.f, po = 0.f;
        #pragma unroll
        for (int z = 0; z < 4; z++){
            pi += g_prep[z][base];
            pj += g_prep[z][base+512];
            pf += g_prep[z][base+1024];
            po += g_prep[z][base+1536];
        }
        pi += bias[n]; pj += bias[512+n]; pf += bias[1024+n]; po += bias[1536+n];
        float c_old = g_c[row*Hd + n];
        float nc = tanhf(c_old*sigf(pf + 1.0f) + sigf(pi)*tanhf(pj));
        g_c[row*Hd + n] = nc;
        out[(size_t)t*Bsz*ODIM + (size_t)row*ODIM + n] = nc * sigf(po);
    }
    for (int idx = bid*256 + tid; idx < Bsz*Md; idx += GRID*256){
        int row = idx >> 7, m = idx & 127;
        size_t base = (size_t)row*NPRE + 2048 + m;
        float s = 0.f;
        #pragma unroll
        for (int z = 0; z < 4; z++) s += g_prep[z][base];
        float rv = g_hent[row*Rd + m] * sigf(s + bias[2048 + m]);
        out[(size_t)t*Bsz*ODIM + (size_t)row*ODIM + Hd + m] = rv;
    }
}

// T1: tail GEMM partials. 128 units = 4 tiles (128x128) x 32 K-chunks (K16).
__device__ void phT1(float* SM, int bid)
{
    if (bid >= 128) return;
    const int tile = bid % 4, z = bid / 4;
    const int rb = (tile >> 1) * 128, nb = (tile & 1) * 128;
    gemm128<2>(SM, (const float*)0, 0, g_wcomb, 256, rb, nb, z*16, 1, g_tp[z], 256);
}

// T2: combine 32 partials + gumbel/argmax + hmem scatter(t) + gather(t+1)
__device__ void phT2(float* SM, int* SI, const float* __restrict__ noise,
                     const float* __restrict__ trans_b, int t, int bid, int tid)
{
    if (bid >= 64) return;
    float (*s_head)[132] = (float(*)[132])SM;
    float (*s_wv)[132]   = (float(*)[132])(SM + 4*132);
    int* s_sel = SI; int* s_selold = SI + 4;
    const int warp = tid >> 5, lane = tid & 31;
    const int b0 = bid * 4;
    const int tn = t + 1;

    if (tid < 4) s_selold[tid] = g_sel[b0 + tid];
    {
        const int rg = tid >> 6;
        const int c4 = (tid & 63) * 4;
        size_t off = (size_t)(b0 + rg)*256 + c4;
        float4 a = {0.f,0.f,0.f,0.f};
        #pragma unroll
        for (int z = 0; z < 32; z++){
            float4 p = ld4(g_tp[z] + off);
            a.x += p.x; a.y += p.y; a.z += p.z; a.w += p.w;
        }
        if (c4 < 128){
            float4 xh = ld4(g_xh + ((size_t)tn*Bsz + b0 + rg)*Md + c4);
            a.x += xh.x; a.y += xh.y; a.z += xh.z; a.w += xh.w;
            *(float4*)&s_head[rg][c4] = a;
        } else {
            float4 tb = ld4(trans_b + (c4 - 128));
            a.x += tb.x; a.y += tb.y; a.z += tb.z; a.w += tb.w;
            *(float4*)&s_wv[rg][c4 - 128] = a;
        }
    }
    __syncthreads();

    if (warp < 4){
        int r = warp;
        float4 hv = *(const float4*)&s_head[r][lane*4];
        float4 nz = ld4(noise + ((size_t)tn*Bsz + b0 + r)*Md + lane*4);
        float v[4];
        v[0] = hv.x - logf(1e-20f - logf(1e-20f + nz.x));
        v[1] = hv.y - logf(1e-20f - logf(1e-20f + nz.y));
        v[2] = hv.z - logf(1e-20f - logf(1e-20f + nz.z));
        v[3] = hv.w - logf(1e-20f - logf(1e-20f + nz.w));
        float best = v[0]; int bi = lane*4;
        #pragma unroll
        for (int c = 1; c < 4; c++) if (v[c] > best){ best = v[c]; bi = lane*4 + c; }
        #pragma unroll
        for (int off = 16; off; off >>= 1){
            float ov = __shfl_xor_sync(0xffffffffu, best, off);
            int   oi = __shfl_xor_sync(0xffffffffu, bi,   off);
            if (ov > best || (ov == best && oi < bi)){ best = ov; bi = oi; }
        }
        if (lane == 0) s_sel[r] = bi;
    } else if (t >= 0){
        int r = warp - 4;
        float4 wv = *(const float4*)&s_wv[r][lane*4];
        int idx = (t < Md) ? t : s_selold[r];
        *(float4*)(g_hmem + ((size_t)(b0+r)*Md + idx)*Rd + lane*4) = wv;
    }
    __syncthreads();

    if (warp < 4){
        int r = warp;
        int sel = s_sel[r];
        float4 h4 = ld4(g_hmem + ((size_t)(b0+r)*Md + sel)*Rd + lane*4);
        *(float4*)(g_hent + (size_t)(b0+r)*Rd + lane*4) = h4;
        if (lane == 0) g_sel[b0+r] = sel;
    }
}

// ---------------- persistent kernel: the whole scan ----------------
__global__ __launch_bounds__(256, 1) void k_persist(
    const float* __restrict__ x, const float* __restrict__ noise,
    const float* __restrict__ Wf, const float* __restrict__ bias,
    const float* __restrict__ W1, const float* __restrict__ bias1,
    const float* __restrict__ trans_b, float* __restrict__ out)
{
    __shared__ __align__(16) float SM[8320];   // 33.3 KB: As[2][16][132] + Bs[2][16][128]
    __shared__ int SI[8];
    const int tid = threadIdx.x, bid = blockIdx.x;
    unsigned gen = 0;

    // prologue: head/argmax for t=0
    phT1(SM, bid);                                   gridbar(++gen, bid, tid);
    phT2(SM, SI, noise, trans_b, -1, bid, tid);      gridbar(++gen, bid, tid);

    for (int t = 0; t < Td; t++){
        phG1(SM, x, W1, t, bid);                     gridbar(++gen, bid, tid);
        phG2(bias1, bid, tid);                       gridbar(++gen, bid, tid);
        phBig(SM, x, Wf, t, bid);                    gridbar(++gen, bid, tid);
        phC(bias, out, t, bid, tid);                 gridbar(++gen, bid, tid);
        if (t < Td - 1){
            phT1(SM, bid);                           gridbar(++gen, bid, tid);
            phT2(SM, SI, noise, trans_b, t, bid, tid); gridbar(++gen, bid, tid);
        }
    }
}

extern "C" void kernel_launch(void* const* d_in, const int* in_sizes, int n_in,
                              void* d_out, int out_size)
{
    const float* x       = (const float*)d_in[0];
    const float* noise   = (const float*)d_in[1];
    const float* W_full  = (const float*)d_in[2];
    const float* bias    = (const float*)d_in[3];
    const float* W_full1 = (const float*)d_in[4];
    const float* bias1   = (const float*)d_in[5];
    const float* fc_w    = (const float*)d_in[6];
    const float* fc_b    = (const float*)d_in[7];
    const float* trans_w = (const float*)d_in[8];
    const float* trans_b = (const float*)d_in[9];
    const float* c_bias  = (const float*)d_in[10];
    const float* hmem_b  = (const float*)d_in[11];
    float* out = (float*)d_out;

    const int initN = Bsz*Md*Rd;
    k_init<<<(initN + 255)/256, 256>>>(fc_w, trans_w, c_bias, hmem_b);
    k_xhead<<<Td*Bsz/64, 256>>>(x, fc_b);
    k_persist<<<GRID, 256>>>(x, noise, W_full, bias, W_full1, bias1, trans_b, out);
}

// round 12
// speedup vs baseline: 1.2135x; 1.2135x over previous
#include <cuda_runtime.h>
#include <math.h>

#define Bsz 256
#define Xd  256
#define Hd  512
#define Rd  128
#define Md  128
#define Td  256
#define XHD 768      // X+H
#define CATD 896     // X+H+R
#define NPRE 2176    // R+4H columns of W_full
#define NG1 640      // R+H
#define ODIM 640
#define GRID 148

typedef unsigned long long ull;

// persistent state / scratch (device globals; no allocation)
__device__ float g_c[Bsz*Hd];
__device__ float g_hmem[Bsz*Md*Rd];
__device__ float g_hent[Bsz*Rd];
__device__ int   g_sel[Bsz];
__device__ float g_fcwxT[Xd*Md];      // fc_w x-part transposed (k-major)
__device__ float g_wcomb[Hd*256];     // [k][0:128]=fc_w c-part^T, [k][128:256]=trans_w^T
__device__ float g_xh[Td*Bsz*Md];     // precomputed x-part of head (+fc_b)
__device__ float g_cc2s[Bsz*NG1];     // scaled [c|hent] part of concat
__device__ float g_g1p[14][Bsz*NG1];  // gates1 K-chunk partials
__device__ float g_prep[4][Bsz*NPRE]; // big GEMM K-chunk partials
__device__ float g_tp[32][Bsz*256];   // tail GEMM K-chunk partials

// grid barrier state
__device__ unsigned g_bar_arrive;
__device__ volatile unsigned g_bar_gen;

__device__ __forceinline__ float sigf(float v){ return 1.0f/(1.0f+expf(-v)); }
__device__ __forceinline__ ull pack2(float v){ ull r; asm("mov.b64 %0, {%1, %1};" : "=l"(r) : "f"(v)); return r; }
__device__ __forceinline__ void ffma2(ull &d, ull a, ull b){ asm("fma.rn.f32x2 %0, %1, %2, %0;" : "+l"(d) : "l"(a), "l"(b)); }
__device__ __forceinline__ float2 unpk(ull v){ float2 f; asm("mov.b64 {%0, %1}, %2;" : "=f"(f.x), "=f"(f.y) : "l"(v)); return f; }
__device__ __forceinline__ float4 ld4(const float* p){ return *(const float4*)p; }

__device__ __forceinline__ void gridbar()
{
    __threadfence();
    __syncthreads();
    if (threadIdx.x == 0){
        unsigned gen = g_bar_gen;
        if (atomicAdd(&g_bar_arrive, 1u) == GRID-1u){
            g_bar_arrive = 0u;
            __threadfence();
            g_bar_gen = gen + 1u;
        } else {
            while (g_bar_gen == gen) { }
            __threadfence();
        }
    }
    __syncthreads();
}

// ---------------- init ----------------
__global__ void k_init(const float* __restrict__ fc_w, const float* __restrict__ trans_w,
                       const float* __restrict__ c_bias, const float* __restrict__ hmem_bias)
{
    int idx = blockIdx.x*blockDim.x + threadIdx.x;
    if (idx == 0){ g_bar_arrive = 0u; g_bar_gen = 0u; }
    if (idx < Bsz*Md*Rd) g_hmem[idx] = hmem_bias[idx & (Md*Rd-1)];
    if (idx < Bsz*Hd)    g_c[idx] = tanhf(c_bias[idx & (Hd-1)]);
    if (idx < Xd*Md){ int k = idx >> 7, m = idx & 127; g_fcwxT[idx] = fc_w[m*XHD + k]; }
    if (idx < Hd*256){
        int k = idx >> 8, c = idx & 255;
        g_wcomb[idx] = (c < 128) ? fc_w[c*XHD + Xd + k] : trans_w[(c-128)*Hd + k];
    }
}

// ---------------- Xh precompute ----------------
__global__ __launch_bounds__(256) void k_xhead(const float* __restrict__ x,
                                               const float* __restrict__ fc_b)
{
    __shared__ __align__(16) float As[16][68];
    __shared__ __align__(16) float Bs[16][128];
    const int tid = threadIdx.x;
    const int rb = blockIdx.x * 64;
    const int tm = tid >> 5;
    const int tn = tid & 31;

    ull acc[8][2] = {};

    const int ar = tid >> 2, akq = tid & 3;
    const float* Ap = x + (size_t)(rb + ar)*Xd + akq*4;
    const int bk = tid >> 4, bm = tid & 15;
    const float* Bp = g_fcwxT + (size_t)bk*Md + bm*8;

    float4 pa = ld4(Ap);
    float4 pb0 = ld4(Bp);
    float4 pb1 = ld4(Bp + 4);

    for (int kt = 0; kt < Xd/16; kt++) {
        As[akq*4+0][ar]=pa.x; As[akq*4+1][ar]=pa.y; As[akq*4+2][ar]=pa.z; As[akq*4+3][ar]=pa.w;
        *(float4*)&Bs[bk][bm*8]   = pb0;
        *(float4*)&Bs[bk][bm*8+4] = pb1;
        __syncthreads();
        if (kt+1 < Xd/16) {
            int k0 = (kt+1)*16;
            pa  = ld4(Ap + k0);
            pb0 = ld4(Bp + (size_t)k0*Md);
            pb1 = ld4(Bp + (size_t)k0*Md + 4);
        }
        #pragma unroll
        for (int kk = 0; kk < 16; kk++) {
            float4 a0 = *(const float4*)&As[kk][tm*8];
            float4 a1 = *(const float4*)&As[kk][tm*8+4];
            ulonglong2 bq = *(const ulonglong2*)&Bs[kk][tn*4];
            float a_[8] = {a0.x,a0.y,a0.z,a0.w,a1.x,a1.y,a1.z,a1.w};
            #pragma unroll
            for (int i=0;i<8;i++){
                ull ap = pack2(a_[i]);
                ffma2(acc[i][0], ap, bq.x);
                ffma2(acc[i][1], ap, bq.y);
            }
        }
        __syncthreads();
    }
    float4 fb = ld4(fc_b + tn*4);
    #pragma unroll
    for (int i=0;i<8;i++){
        int row = rb + tm*8 + i;
        float2 l0 = unpk(acc[i][0]), l1 = unpk(acc[i][1]);
        float4 o = { l0.x+fb.x, l0.y+fb.y, l1.x+fb.z, l1.y+fb.w };
        *(float4*)(g_xh + (size_t)row*Md + tn*4) = o;
    }
}

// ============ unified 128x128 GEMM unit (8x8 thread tile, FFMA2, double-buffered) ====
// B fragment is SPLIT: columns [tn*4 .. tn*4+3] and [64+tn*4 .. 64+tn*4+3] so the
// 16 lane addresses stride 16B and cover all smem bank slots (conflict-free floor).

template<int MODE>
__device__ __forceinline__ float4 loadA(const float* __restrict__ x, int t, int row, int kg)
{
    if (MODE == 0){            // concat [x | c | hent]
        const float* p;
        if (kg < Xd)       p = x + ((size_t)t*Bsz + row)*Xd + kg;
        else if (kg < XHD) p = g_c + (size_t)row*Hd + (kg - Xd);
        else               p = g_hent + (size_t)row*Rd + (kg - XHD);
        return ld4(p);
    } else if (MODE == 1){     // [x | cc2s]
        const float* p = (kg < Xd) ? (x + ((size_t)t*Bsz + row)*Xd + kg)
                                   : (g_cc2s + (size_t)row*NG1 + (kg - Xd));
        return ld4(p);
    } else {                   // g_c
        return ld4(g_c + (size_t)row*Hd + kg);
    }
}

template<int MODE>
__device__ void gemm128(float* SM, const float* __restrict__ x, int t,
                        const float* __restrict__ Bm, int ldb,
                        int rb, int nb, int kbase, int nkt,
                        float* __restrict__ outP, int ldo)
{
    float (*As)[16][132] = (float(*)[16][132])SM;
    float (*Bs)[16][128] = (float(*)[16][128])(SM + 2*16*132);
    const int tid = threadIdx.x;
    const int tm = tid >> 4, tn = tid & 15;
    const int ia0 = tid*2, ia1 = tid*2+1;
    const int ar0 = ia0 >> 2, ak0 = (ia0 & 3)*4;
    const int ar1 = ia1 >> 2, ak1 = (ia1 & 3)*4;
    const int bk0 = ia0 >> 5, bc0 = (ia0 & 31)*4;
    const int bk1 = ia1 >> 5, bc1 = (ia1 & 31)*4;

    ull acc[8][4] = {};

    float4 pa0 = loadA<MODE>(x, t, rb+ar0, kbase + ak0);
    float4 pa1 = loadA<MODE>(x, t, rb+ar1, kbase + ak1);
    float4 pb0 = ld4(Bm + (size_t)(kbase + bk0)*ldb + nb + bc0);
    float4 pb1 = ld4(Bm + (size_t)(kbase + bk1)*ldb + nb + bc1);

    for (int kt = 0; kt < nkt; kt++){
        const int p = kt & 1;
        As[p][ak0+0][ar0]=pa0.x; As[p][ak0+1][ar0]=pa0.y; As[p][ak0+2][ar0]=pa0.z; As[p][ak0+3][ar0]=pa0.w;
        As[p][ak1+0][ar1]=pa1.x; As[p][ak1+1][ar1]=pa1.y; As[p][ak1+2][ar1]=pa1.z; As[p][ak1+3][ar1]=pa1.w;
        *(float4*)&Bs[p][bk0][bc0] = pb0;
        *(float4*)&Bs[p][bk1][bc1] = pb1;
        __syncthreads();
        if (kt+1 < nkt){
            int k0 = kbase + (kt+1)*16;
            pa0 = loadA<MODE>(x, t, rb+ar0, k0 + ak0);
            pa1 = loadA<MODE>(x, t, rb+ar1, k0 + ak1);
            pb0 = ld4(Bm + (size_t)(k0 + bk0)*ldb + nb + bc0);
            pb1 = ld4(Bm + (size_t)(k0 + bk1)*ldb + nb + bc1);
        }
        #pragma unroll
        for (int kk = 0; kk < 16; kk++){
            float4 a0 = *(const float4*)&As[p][kk][tm*8];
            float4 a1 = *(const float4*)&As[p][kk][tm*8+4];
            ulonglong2 b0 = *(const ulonglong2*)&Bs[p][kk][tn*4];        // cols tn*4..+3
            ulonglong2 b1 = *(const ulonglong2*)&Bs[p][kk][64 + tn*4];   // cols 64+tn*4..+3
            float av[8] = {a0.x,a0.y,a0.z,a0.w,a1.x,a1.y,a1.z,a1.w};
            ull bq[4] = {b0.x,b0.y,b1.x,b1.y};
            #pragma unroll
            for (int r = 0; r < 8; r++){
                ull ap = pack2(av[r]);
                ffma2(acc[r][0], ap, bq[0]);
                ffma2(acc[r][1], ap, bq[1]);
                ffma2(acc[r][2], ap, bq[2]);
                ffma2(acc[r][3], ap, bq[3]);
            }
        }
        __syncthreads();
    }
    #pragma unroll
    for (int r = 0; r < 8; r++){
        float2 c0 = unpk(acc[r][0]), c1 = unpk(acc[r][1]);
        float2 c2 = unpk(acc[r][2]), c3 = unpk(acc[r][3]);
        float* op = outP + (size_t)(rb + tm*8 + r)*ldo + nb + tn*4;
        float4 o0 = {c0.x, c0.y, c1.x, c1.y};   // cols tn*4..+3
        float4 o1 = {c2.x, c2.y, c3.x, c3.y};   // cols 64+tn*4..+3
        *(float4*)op = o0;
        *(float4*)(op + 64) = o1;
    }
}

// =========================== persistent-kernel phases ===============================

// G1: gates1 partials. 140 units = 10 tiles (128x128) x 14 K-chunks (K64).
__device__ void phG1(float* SM, const float* __restrict__ x,
                     const float* __restrict__ W1, int t, int bid)
{
    if (bid >= 140) return;
    const int tile = bid % 10, z = bid / 10;
    const int rb = (tile / 5) * 128, nb = (tile % 5) * 128;
    gemm128<0>(SM, x, t, W1, NG1, rb, nb, z*64, 4, g_g1p[z], NG1);
}

// G2: combine 14 partials, sigmoid-scale [c|hent] -> g_cc2s
__device__ void phG2(const float* __restrict__ bias1, int bid, int tid)
{
    for (int idx = bid*256 + tid; idx < Bsz*160; idx += GRID*256){
        int row = idx / 160;
        int c = (idx - row*160) * 4;
        size_t o = (size_t)row*NG1 + c;
        float4 s = ld4(g_g1p[0] + o);
        #pragma unroll
        for (int z = 1; z < 14; z++){
            float4 p = ld4(g_g1p[z] + o);
            s.x += p.x; s.y += p.y; s.z += p.z; s.w += p.w;
        }
        float4 b = ld4(bias1 + c);
        float4 cv = (c < Hd) ? ld4(g_c + (size_t)row*Hd + c)
                             : ld4(g_hent + (size_t)row*Rd + (c - Hd));
        float4 r;
        r.x = cv.x * sigf(s.x + b.x);
        r.y = cv.y * sigf(s.y + b.y);
        r.z = cv.z * sigf(s.z + b.z);
        r.w = cv.w * sigf(s.w + b.w);
        *(float4*)(g_cc2s + o) = r;
    }
}

// Big: 136 units = 34 tiles (128x128 plain cols) x 4 K-chunks (K224).
__device__ void phBig(float* SM, const float* __restrict__ x,
                      const float* __restrict__ Wf, int t, int bid)
{
    if (bid >= 136) return;
    const int tile = bid % 34, z = bid / 34;
    const int rb = (tile / 17) * 128, nb = (tile % 17) * 128;
    gemm128<1>(SM, x, t, Wf, NPRE, rb, nb, z*224, 14, g_prep[z], NPRE);
}

// C: combine 4 big partials + LSTM / r epilogue -> g_c, out
__device__ void phC(const float* __restrict__ bias, float* __restrict__ out,
                    int t, int bid, int tid)
{
    for (int idx = bid*256 + tid; idx < Bsz*Hd; idx += GRID*256){
        int row = idx >> 9, n = idx & 511;
        size_t base = (size_t)row*NPRE + n;
        float pi = 0.f, pj = 0.f, pf = 0.f, po = 0.f;
        #pragma unroll
        for (int z = 0; z < 4; z++){
            pi += g_prep[z][base];
            pj += g_prep[z][base+512];
            pf += g_prep[z][base+1024];
            po += g_prep[z][base+1536];
        }
        pi += bias[n]; pj += bias[512+n]; pf += bias[1024+n]; po += bias[1536+n];
        float c_old = g_c[row*Hd + n];
        float nc = tanhf(c_old*sigf(pf + 1.0f) + sigf(pi)*tanhf(pj));
        g_c[row*Hd + n] = nc;
        out[(size_t)t*Bsz*ODIM + (size_t)row*ODIM + n] = nc * sigf(po);
    }
    for (int idx = bid*256 + tid; idx < Bsz*Md; idx += GRID*256){
        int row = idx >> 7, m = idx & 127;
        size_t base = (size_t)row*NPRE + 2048 + m;
        float s = 0.f;
        #pragma unroll
        for (int z = 0; z < 4; z++) s += g_prep[z][base];
        float rv = g_hent[row*Rd + m] * sigf(s + bias[2048 + m]);
        out[(size_t)t*Bsz*ODIM + (size_t)row*ODIM + Hd + m] = rv;
    }
}

// T1: tail GEMM partials. 128 units = 4 tiles (128x128) x 32 K-chunks (K16).
__device__ void phT1(float* SM, int bid)
{
    if (bid >= 128) return;
    const int tile = bid % 4, z = bid / 4;
    const int rb = (tile >> 1) * 128, nb = (tile & 1) * 128;
    gemm128<2>(SM, (const float*)0, 0, g_wcomb, 256, rb, nb, z*16, 1, g_tp[z], 256);
}

// T2: combine 32 partials + gumbel/argmax + hmem scatter(t) + gather(t+1)
__device__ void phT2(float* SM, int* SI, const float* __restrict__ noise,
                     const float* __restrict__ trans_b, int t, int bid, int tid)
{
    if (bid >= 64) return;
    float (*s_head)[132] = (float(*)[132])SM;
    float (*s_wv)[132]   = (float(*)[132])(SM + 4*132);
    int* s_sel = SI; int* s_selold = SI + 4;
    const int warp = tid >> 5, lane = tid & 31;
    const int b0 = bid * 4;
    const int tn = t + 1;

    if (tid < 4) s_selold[tid] = g_sel[b0 + tid];
    {
        const int rg = tid >> 6;
        const int c4 = (tid & 63) * 4;
        size_t off = (size_t)(b0 + rg)*256 + c4;
        float4 a = {0.f,0.f,0.f,0.f};
        #pragma unroll
        for (int z = 0; z < 32; z++){
            float4 p = ld4(g_tp[z] + off);
            a.x += p.x; a.y += p.y; a.z += p.z; a.w += p.w;
        }
        if (c4 < 128){
            float4 xh = ld4(g_xh + ((size_t)tn*Bsz + b0 + rg)*Md + c4);
            a.x += xh.x; a.y += xh.y; a.z += xh.z; a.w += xh.w;
            *(float4*)&s_head[rg][c4] = a;
        } else {
            float4 tb = ld4(trans_b + (c4 - 128));
            a.x += tb.x; a.y += tb.y; a.z += tb.z; a.w += tb.w;
            *(float4*)&s_wv[rg][c4 - 128] = a;
        }
    }
    __syncthreads();

    if (warp < 4){
        int r = warp;
        float4 hv = *(const float4*)&s_head[r][lane*4];
        float4 nz = ld4(noise + ((size_t)tn*Bsz + b0 + r)*Md + lane*4);
        float v[4];
        v[0] = hv.x - logf(1e-20f - logf(1e-20f + nz.x));
        v[1] = hv.y - logf(1e-20f - logf(1e-20f + nz.y));
        v[2] = hv.z - logf(1e-20f - logf(1e-20f + nz.z));
        v[3] = hv.w - logf(1e-20f - logf(1e-20f + nz.w));
        float best = v[0]; int bi = lane*4;
        #pragma unroll
        for (int c = 1; c < 4; c++) if (v[c] > best){ best = v[c]; bi = lane*4 + c; }
        #pragma unroll
        for (int off = 16; off; off >>= 1){
            float ov = __shfl_xor_sync(0xffffffffu, best, off);
            int   oi = __shfl_xor_sync(0xffffffffu, bi,   off);
            if (ov > best || (ov == best && oi < bi)){ best = ov; bi = oi; }
        }
        if (lane == 0) s_sel[r] = bi;
    } else if (t >= 0){
        int r = warp - 4;
        float4 wv = *(const float4*)&s_wv[r][lane*4];
        int idx = (t < Md) ? t : s_selold[r];
        *(float4*)(g_hmem + ((size_t)(b0+r)*Md + idx)*Rd + lane*4) = wv;
    }
    __syncthreads();

    if (warp < 4){
        int r = warp;
        int sel = s_sel[r];
        float4 h4 = ld4(g_hmem + ((size_t)(b0+r)*Md + sel)*Rd + lane*4);
        *(float4*)(g_hent + (size_t)(b0+r)*Rd + lane*4) = h4;
        if (lane == 0) g_sel[b0+r] = sel;
    }
}

// ---------------- persistent kernel: the whole scan ----------------
__global__ __launch_bounds__(256, 1) void k_persist(
    const float* __restrict__ x, const float* __restrict__ noise,
    const float* __restrict__ Wf, const float* __restrict__ bias,
    const float* __restrict__ W1, const float* __restrict__ bias1,
    const float* __restrict__ trans_b, float* __restrict__ out)
{
    __shared__ __align__(16) float SM[8320];   // 33.3 KB: As[2][16][132] + Bs[2][16][128]
    __shared__ int SI[8];
    const int tid = threadIdx.x, bid = blockIdx.x;

    // prologue: head/argmax for t=0
    phT1(SM, bid);                                   gridbar();
    phT2(SM, SI, noise, trans_b, -1, bid, tid);      gridbar();

    for (int t = 0; t < Td; t++){
        phG1(SM, x, W1, t, bid);                     gridbar();
        phG2(bias1, bid, tid);                       gridbar();
        phBig(SM, x, Wf, t, bid);                    gridbar();
        phC(bias, out, t, bid, tid);                 gridbar();
        if (t < Td - 1){
            phT1(SM, bid);                           gridbar();
            phT2(SM, SI, noise, trans_b, t, bid, tid); gridbar();
        }
    }
}

extern "C" void kernel_launch(void* const* d_in, const int* in_sizes, int n_in,
                              void* d_out, int out_size)
{
    const float* x       = (const float*)d_in[0];
    const float* noise   = (const float*)d_in[1];
    const float* W_full  = (const float*)d_in[2];
    const float* bias    = (const float*)d_in[3];
    const float* W_full1 = (const float*)d_in[4];
    const float* bias1   = (const float*)d_in[5];
    const float* fc_w    = (const float*)d_in[6];
    const float* fc_b    = (const float*)d_in[7];
    const float* trans_w = (const float*)d_in[8];
    const float* trans_b = (const float*)d_in[9];
    const float* c_bias  = (const float*)d_in[10];
    const float* hmem_b  = (const float*)d_in[11];
    float* out = (float*)d_out;

    const int initN = Bsz*Md*Rd;
    k_init<<<(initN + 255)/256, 256>>>(fc_w, trans_w, c_bias, hmem_b);
    k_xhead<<<Td*Bsz/64, 256>>>(x, fc_b);
    k_persist<<<GRID, 256>>>(x, noise, W_full, bias, W_full1, bias1, trans_b, out);
}